// round 5
// baseline (speedup 1.0000x reference)
#include <cuda_runtime.h>
#include <cuda_bf16.h>
#include <mma.h>
#include <math.h>

using namespace nvcuda;

// ---------------------------------------------------------------------------
// Problem constants
// ---------------------------------------------------------------------------
#define T_TOK  1024
#define HID    1024
#define NH     16
#define NKV    4
#define HD     64
#define QKV_N  1536
#define NE     64
#define NG     8
#define INTER  512
#define NA     (T_TOK*NG)
#define NA_PAD 16384

// GEMM tiling
#define BM 128
#define BN 128
#define BK 32
#define LDA_S 40
#define LDB_S 136

// attention smem leading dims
#define LDH 72
#define LDF 68

// ---------------------------------------------------------------------------
// Scratch (static device globals)
// ---------------------------------------------------------------------------
__device__ __nv_bfloat16 g_hb   [T_TOK*HID];
__device__ float         g_qkv  [T_TOK*QKV_N];
__device__ __nv_bfloat16 g_qb   [T_TOK*NH*HD];
__device__ __nv_bfloat16 g_kb   [T_TOK*NKV*HD];
__device__ __nv_bfloat16 g_vb   [T_TOK*NKV*HD];
__device__ __nv_bfloat16 g_attnb[T_TOK*NH*HD];
__device__ float         g_h2   [T_TOK*HID];
__device__ __nv_bfloat16 g_h2b  [T_TOK*HID];
__device__ float         g_gu   [NA_PAD*1024];
__device__ __nv_bfloat16 g_actb [NA_PAD*INTER];
__device__ int   g_cnt [NE];
__device__ int   g_off [NE];
__device__ int   g_fill[NE];
__device__ int   g_total;
__device__ int   g_selid[NA];
__device__ float g_selw [NA];
__device__ int   g_tok  [NA_PAD];
__device__ float g_w    [NA_PAD];

// ---------------------------------------------------------------------------
// WMMA types + cp.async helpers
// ---------------------------------------------------------------------------
using FragA  = wmma::fragment<wmma::matrix_a, 16, 16, 16, __nv_bfloat16, wmma::row_major>;
using FragB  = wmma::fragment<wmma::matrix_b, 16, 16, 16, __nv_bfloat16, wmma::row_major>;
using FragBc = wmma::fragment<wmma::matrix_b, 16, 16, 16, __nv_bfloat16, wmma::col_major>;
using FragC  = wmma::fragment<wmma::accumulator, 16, 16, 16, float>;

__device__ __forceinline__ void cp16(unsigned dst, const void* src) {
    asm volatile("cp.async.cg.shared.global [%0], [%1], 16;\n" :: "r"(dst), "l"(src));
}
__device__ __forceinline__ void cp16z(unsigned dst, const void* src, int valid) {
    asm volatile("cp.async.cg.shared.global [%0], [%1], 16, %2;\n"
                 :: "r"(dst), "l"(src), "r"(valid ? 16 : 0));
}
#define CP_COMMIT() asm volatile("cp.async.commit_group;\n")
template<int N> __device__ __forceinline__ void cp_wait() {
    asm volatile("cp.async.wait_group %0;\n" :: "n"(N));
}

__device__ __forceinline__ uint4 f8_to_bf8(float4 a, float4 b) {
    __nv_bfloat162 p0 = __floats2bfloat162_rn(a.x, a.y);
    __nv_bfloat162 p1 = __floats2bfloat162_rn(a.z, a.w);
    __nv_bfloat162 p2 = __floats2bfloat162_rn(b.x, b.y);
    __nv_bfloat162 p3 = __floats2bfloat162_rn(b.z, b.w);
    uint4 r;
    r.x = *reinterpret_cast<unsigned*>(&p0);
    r.y = *reinterpret_cast<unsigned*>(&p1);
    r.z = *reinterpret_cast<unsigned*>(&p2);
    r.w = *reinterpret_cast<unsigned*>(&p3);
    return r;
}

struct Breg { float4 a0, a1, b0, b1; };

__device__ __forceinline__ void mma_tile(const __nv_bfloat16* As, const __nv_bfloat16* Bs,
                                         FragC (&acc)[2][4], int wm, int wn) {
#pragma unroll
    for (int kk = 0; kk < BK; kk += 16) {
        FragA a[2];
        FragB b[4];
#pragma unroll
        for (int i = 0; i < 2; i++)
            wmma::load_matrix_sync(a[i], As + (wm * 32 + i * 16) * LDA_S + kk, LDA_S);
#pragma unroll
        for (int j = 0; j < 4; j++)
            wmma::load_matrix_sync(b[j], Bs + kk * LDB_S + wn * 64 + j * 16, LDB_S);
#pragma unroll
        for (int i = 0; i < 2; i++)
#pragma unroll
            for (int j = 0; j < 4; j++)
                wmma::mma_sync(acc[i][j], a[i], b[j], acc[i][j]);
    }
}

// ---------------------------------------------------------------------------
// RMSNorm
// ---------------------------------------------------------------------------
__global__ void k_rmsnorm(const float* __restrict__ in,
                          const float* __restrict__ w,
                          float* __restrict__ outf,
                          __nv_bfloat16* __restrict__ outb) {
    int t = blockIdx.x;
    const float* x = in + (size_t)t * HID;
    float ss = 0.f;
    for (int i = threadIdx.x; i < HID; i += 256) { float v = x[i]; ss += v * v; }
#pragma unroll
    for (int o = 16; o; o >>= 1) ss += __shfl_xor_sync(0xffffffffu, ss, o);
    __shared__ float red[8];
    __shared__ float stot;
    if ((threadIdx.x & 31) == 0) red[threadIdx.x >> 5] = ss;
    __syncthreads();
    if (threadIdx.x == 0) {
        float s = 0.f;
#pragma unroll
        for (int i = 0; i < 8; i++) s += red[i];
        stot = rsqrtf(s * (1.f / HID) + 1e-6f);
    }
    __syncthreads();
    float sc = stot;
    for (int i = threadIdx.x; i < HID; i += 256) {
        float v = x[i] * sc * w[i];
        if (outf) outf[(size_t)t * HID + i] = v;
        if (outb) outb[(size_t)t * HID + i] = __float2bfloat16(v);
    }
}

// ---------------------------------------------------------------------------
// Dense bf16 GEMM, pipelined: cp.async A (2 stages), 2-deep reg prefetch B.
// ---------------------------------------------------------------------------
__global__ void __launch_bounds__(256) k_gemm_bf16(
        const __nv_bfloat16* __restrict__ A, const float* __restrict__ B,
        float* __restrict__ C, const float* __restrict__ R,
        int M, int N, int K) {
    __shared__ __nv_bfloat16 As[2][BM * LDA_S];
    __shared__ __nv_bfloat16 Bs[2][BK * LDB_S];
    int tid = threadIdx.x;
    int warp = tid >> 5;
    int wm = warp & 3, wn = warp >> 2;
    int m0 = blockIdx.y * BM, n0 = blockIdx.x * BN;

    int a_r = tid >> 2, a_c = (tid & 3) * 8;
    int b_r = tid >> 4, b_c = (tid & 15) * 8;
    unsigned sA = (unsigned)__cvta_generic_to_shared(&As[0][0]);

    FragC acc[2][4];
    if (R) {
#pragma unroll
        for (int i = 0; i < 2; i++)
#pragma unroll
            for (int j = 0; j < 4; j++)
                wmma::load_matrix_sync(acc[i][j],
                    R + (size_t)(m0 + wm * 32 + i * 16) * N + n0 + wn * 64 + j * 16,
                    N, wmma::mem_row_major);
    } else {
#pragma unroll
        for (int i = 0; i < 2; i++)
#pragma unroll
            for (int j = 0; j < 4; j++) wmma::fill_fragment(acc[i][j], 0.f);
    }

    auto cpA = [&](int stage, int k0) {
        unsigned d = sA + (unsigned)(stage * BM * LDA_S + a_r * LDA_S + a_c) * 2;
        cp16(d, &A[(size_t)(m0 + a_r) * K + k0 + a_c]);
        cp16(d + 64 * LDA_S * 2, &A[(size_t)(m0 + a_r + 64) * K + k0 + a_c]);
    };
    auto ldgB = [&](Breg& r, int k0) {
        const float* p0 = &B[(size_t)(k0 + b_r) * N + n0 + b_c];
        r.a0 = *(const float4*)p0; r.a1 = *(const float4*)(p0 + 4);
        const float* p1 = &B[(size_t)(k0 + b_r + 16) * N + n0 + b_c];
        r.b0 = *(const float4*)p1; r.b1 = *(const float4*)(p1 + 4);
    };
    auto stsB = [&](const Breg& r, int buf) {
        *(uint4*)&Bs[buf][b_r * LDB_S + b_c] = f8_to_bf8(r.a0, r.a1);
        *(uint4*)&Bs[buf][(b_r + 16) * LDB_S + b_c] = f8_to_bf8(r.b0, r.b1);
    };

    const int n = K / BK;
    Breg r0, r1;
    cpA(0, 0); CP_COMMIT();
    cpA(1, BK); CP_COMMIT();
    ldgB(r0, 0); ldgB(r1, BK);
    stsB(r0, 0);
    if (n > 2) ldgB(r0, 2 * BK);
    cp_wait<1>(); __syncthreads();

    for (int it = 0; it < n; it++) {
        mma_tile(As[it & 1], Bs[it & 1], acc, wm, wn);
        if (it + 1 < n) {
            Breg& rr = (it & 1) ? r0 : r1;
            stsB(rr, (it + 1) & 1);
            if (it + 3 < n) ldgB(rr, (it + 3) * BK);
            cp_wait<0>();
            __syncthreads();
            if (it + 2 < n) { cpA(it & 1, (it + 2) * BK); CP_COMMIT(); }
        }
    }
#pragma unroll
    for (int i = 0; i < 2; i++)
#pragma unroll
        for (int j = 0; j < 4; j++)
            wmma::store_matrix_sync(
                C + (size_t)(m0 + wm * 32 + i * 16) * N + n0 + wn * 64 + j * 16,
                acc[i][j], N, wmma::mem_row_major);
}

// ---------------------------------------------------------------------------
// Per-head RMSNorm + RoPE (q,k) and copy (v) -> bf16
// ---------------------------------------------------------------------------
__global__ void k_qk_prep(const int* __restrict__ pos,
                          const float* __restrict__ qnw,
                          const float* __restrict__ knw) {
    int hh = blockIdx.x;
    int t  = blockIdx.y;
    int i  = threadIdx.x;
    if (hh >= NH + NKV) {
        int vh = hh - NH - NKV;
        const float* src = g_qkv + (size_t)t * QKV_N + (NH + NKV) * HD + vh * HD;
        __nv_bfloat16* dst = g_vb + (size_t)t * (NKV * HD) + vh * HD;
        dst[i]      = __float2bfloat16(src[i]);
        dst[i + 32] = __float2bfloat16(src[i + 32]);
        return;
    }
    const float* src; __nv_bfloat16* dst; const float* w;
    if (hh < NH) {
        src = g_qkv + (size_t)t * QKV_N + hh * HD;
        dst = g_qb  + (size_t)t * (NH * HD) + hh * HD;
        w = qnw;
    } else {
        int kh = hh - NH;
        src = g_qkv + (size_t)t * QKV_N + NH * HD + kh * HD;
        dst = g_kb  + (size_t)t * (NKV * HD) + kh * HD;
        w = knw;
    }
    float x1 = src[i], x2 = src[i + 32];
    float ss = x1 * x1 + x2 * x2;
#pragma unroll
    for (int o = 16; o; o >>= 1) ss += __shfl_xor_sync(0xffffffffu, ss, o);
    float sc = rsqrtf(ss * (1.f / 64.f) + 1e-6f);
    x1 *= sc * w[i];
    x2 *= sc * w[i + 32];
    float p = (float)pos[t];
    float inv = powf(10000.f, -(float)i * (1.f / 32.f));
    float f = p * inv;
    float c = cosf(f), s = sinf(f);
    dst[i]      = __float2bfloat16(x1 * c - x2 * s);
    dst[i + 32] = __float2bfloat16(x2 * c + x1 * s);
}

// ---------------------------------------------------------------------------
// Flash attention, bf16 WMMA (unchanged this round)
// ---------------------------------------------------------------------------
__global__ void __launch_bounds__(128) k_attn_wmma() {
    extern __shared__ char smraw[];
    __nv_bfloat16* Qs = (__nv_bfloat16*)smraw;
    __nv_bfloat16* Ks = Qs + 64 * LDH;
    __nv_bfloat16* Vs = Ks + 64 * LDH;
    __nv_bfloat16* Ps = Vs + 64 * LDH;
    float* Ss   = (float*)(Ps + 64 * LDH);
    float* Os   = Ss + 64 * LDF;
    float* mrow = Os + 64 * LDF;
    float* lrow = mrow + 64;
    float* red1 = lrow + 64;
    float* red2 = red1 + 128;

    int h   = blockIdx.y;
    int m0  = blockIdx.x * 64;
    int kvh = h >> 2;
    int tid  = threadIdx.x;
    int warp = tid >> 5;

#pragma unroll
    for (int j = 0; j < 4; j++) {
        int idx = tid + j * 128;
        int r = idx >> 3, c = (idx & 7) * 8;
        *(uint4*)&Qs[r * LDH + c] =
            *(const uint4*)&g_qb[(size_t)(m0 + r) * (NH * HD) + h * HD + c];
    }
    for (int i = tid; i < 64 * LDF; i += 128) Os[i] = 0.f;
    if (tid < 64) { mrow[tid] = -INFINITY; lrow[tid] = 0.f; }

    int row  = tid & 63;
    int half = tid >> 6;
    int c0   = half * 32;
    int rglob = m0 + row;

    int ntiles = (m0 >> 6) + 1;
    for (int nt = 0; nt < ntiles; nt++) {
        int n0 = nt * 64;
        __syncthreads();
#pragma unroll
        for (int j = 0; j < 4; j++) {
            int idx = tid + j * 128;
            int r = idx >> 3, c = (idx & 7) * 8;
            *(uint4*)&Ks[r * LDH + c] =
                *(const uint4*)&g_kb[(size_t)(n0 + r) * (NKV * HD) + kvh * HD + c];
            *(uint4*)&Vs[r * LDH + c] =
                *(const uint4*)&g_vb[(size_t)(n0 + r) * (NKV * HD) + kvh * HD + c];
        }
        __syncthreads();

#pragma unroll
        for (int n = 0; n < 4; n++) {
            FragC s;
            wmma::fill_fragment(s, 0.f);
#pragma unroll
            for (int k = 0; k < 4; k++) {
                FragA a;
                FragBc b;
                wmma::load_matrix_sync(a, Qs + (warp * 16) * LDH + k * 16, LDH);
                wmma::load_matrix_sync(b, Ks + (n * 16) * LDH + k * 16, LDH);
                wmma::mma_sync(s, a, b, s);
            }
            wmma::store_matrix_sync(Ss + (warp * 16) * LDF + n * 16, s, LDF,
                                    wmma::mem_row_major);
        }
        __syncthreads();

        float mx = -INFINITY;
#pragma unroll
        for (int c = 0; c < 32; c++) {
            int cg = n0 + c0 + c;
            float v = (cg <= rglob) ? Ss[row * LDF + c0 + c] * 0.125f : -INFINITY;
            mx = fmaxf(mx, v);
        }
        red1[row * 2 + half] = mx;
        __syncthreads();

        float tmax = fmaxf(red1[row * 2], red1[row * 2 + 1]);
        float mold = mrow[row];
        float mn = fmaxf(mold, tmax);
        float alpha = __expf(mold - mn);
        float ps = 0.f;
#pragma unroll
        for (int c = 0; c < 32; c++) {
            int cg = n0 + c0 + c;
            float p = (cg <= rglob) ? __expf(Ss[row * LDF + c0 + c] * 0.125f - mn) : 0.f;
            Ps[row * LDH + c0 + c] = __float2bfloat16(p);
            ps += p;
        }
        red2[row * 2 + half] = ps;
#pragma unroll
        for (int c = 0; c < 32; c++) Os[row * LDF + c0 + c] *= alpha;
        __syncthreads();
        if (half == 0) {
            lrow[row] = lrow[row] * alpha + red2[row * 2] + red2[row * 2 + 1];
            mrow[row] = mn;
        }

#pragma unroll
        for (int n = 0; n < 4; n++) {
            FragC acc;
            wmma::fill_fragment(acc, 0.f);
#pragma unroll
            for (int k = 0; k < 4; k++) {
                FragA a;
                FragB b;
                wmma::load_matrix_sync(a, Ps + (warp * 16) * LDH + k * 16, LDH);
                wmma::load_matrix_sync(b, Vs + (k * 16) * LDH + n * 16, LDH);
                wmma::mma_sync(acc, a, b, acc);
            }
            FragC o;
            wmma::load_matrix_sync(o, Os + (warp * 16) * LDF + n * 16, LDF,
                                   wmma::mem_row_major);
#pragma unroll
            for (int e = 0; e < o.num_elements; e++) o.x[e] += acc.x[e];
            wmma::store_matrix_sync(Os + (warp * 16) * LDF + n * 16, o, LDF,
                                    wmma::mem_row_major);
        }
    }
    __syncthreads();

    float inv = 1.f / lrow[row];
#pragma unroll
    for (int c = 0; c < 32; c++)
        g_attnb[(size_t)(m0 + row) * (NH * HD) + h * HD + c0 + c] =
            __float2bfloat16(Os[row * LDF + c0 + c] * inv);
}

// ---------------------------------------------------------------------------
// Routing
// ---------------------------------------------------------------------------
__global__ void k_zero() {
    int i = threadIdx.x;
    if (i < NE) { g_cnt[i] = 0; g_fill[i] = 0; }
}

__global__ void k_route(const float* __restrict__ H2, const float* __restrict__ Wg) {
    int t = blockIdx.x;
    int e = threadIdx.x;
    __shared__ float sh[HID];
    for (int i = e; i < HID; i += 64) sh[i] = H2[(size_t)t * HID + i];
    __syncthreads();
    float a0 = 0, a1 = 0, a2 = 0, a3 = 0;
    for (int k = 0; k < HID; k += 4) {
        a0 += sh[k]     * Wg[(size_t)k       * NE + e];
        a1 += sh[k + 1] * Wg[(size_t)(k + 1) * NE + e];
        a2 += sh[k + 2] * Wg[(size_t)(k + 2) * NE + e];
        a3 += sh[k + 3] * Wg[(size_t)(k + 3) * NE + e];
    }
    __shared__ float logits[NE];
    logits[e] = (a0 + a1) + (a2 + a3);
    __syncthreads();
    if (e == 0) {
        float sv[NG]; int si[NG];
#pragma unroll
        for (int g = 0; g < NG; g++) {
            float best = logits[g * 8]; int bi = g * 8;
#pragma unroll
            for (int j = 1; j < 8; j++) {
                float v = logits[g * 8 + j];
                if (v > best) { best = v; bi = g * 8 + j; }
            }
            sv[g] = best; si[g] = bi;
        }
        float m = sv[0];
#pragma unroll
        for (int g = 1; g < NG; g++) m = fmaxf(m, sv[g]);
        float sum = 0.f, p[NG];
#pragma unroll
        for (int g = 0; g < NG; g++) { p[g] = expf(sv[g] - m); sum += p[g]; }
        float is = 1.f / sum;
#pragma unroll
        for (int g = 0; g < NG; g++) {
            g_selid[t * NG + g] = si[g];
            g_selw [t * NG + g] = p[g] * is;
            atomicAdd(&g_cnt[si[g]], 1);
        }
    }
}

__global__ void k_scan() {
    int s = 0;
    for (int e = 0; e < NE; e++) { g_off[e] = s; s += (g_cnt[e] + BM - 1) & ~(BM - 1); }
    g_total = s;
}

__global__ void k_scatter() {
    int t = blockIdx.x, g = threadIdx.x;
    int e = g_selid[t * NG + g];
    int slot = atomicAdd(&g_fill[e], 1);
    int row = g_off[e] + slot;
    g_tok[row] = t;
    g_w[row]   = g_selw[t * NG + g];
}

// ---------------------------------------------------------------------------
// MoE GEMM 1 (bf16, pipelined): gu = H2b[tok] @ Wgu[e]
// ---------------------------------------------------------------------------
__global__ void __launch_bounds__(256) k_moe1(const __nv_bfloat16* __restrict__ Ab,
                                              const float* __restrict__ Wgu) {
    int e = blockIdx.z;
    int cnt = g_cnt[e];
    int m0 = blockIdx.y * BM;
    if (m0 >= cnt) return;
    int off = g_off[e];
    int n0 = blockIdx.x * BN;
    const float* B = Wgu + (size_t)e * (HID * 1024);

    __shared__ __nv_bfloat16 As[2][BM * LDA_S];
    __shared__ __nv_bfloat16 Bs[2][BK * LDB_S];
    __shared__ int stok[BM];
    int tid = threadIdx.x;
    int warp = tid >> 5;
    int wm = warp & 3, wn = warp >> 2;
    if (tid < BM) stok[tid] = (m0 + tid < cnt) ? g_tok[off + m0 + tid] : -1;
    __syncthreads();

    int a_r = tid >> 2, a_c = (tid & 3) * 8;
    int b_r = tid >> 4, b_c = (tid & 15) * 8;
    int tk0 = stok[a_r], tk1 = stok[a_r + 64];
    const __nv_bfloat16* abase0 = Ab + (size_t)((tk0 >= 0) ? tk0 : 0) * HID;
    const __nv_bfloat16* abase1 = Ab + (size_t)((tk1 >= 0) ? tk1 : 0) * HID;
    unsigned sA = (unsigned)__cvta_generic_to_shared(&As[0][0]);

    FragC acc[2][4];
#pragma unroll
    for (int i = 0; i < 2; i++)
#pragma unroll
        for (int j = 0; j < 4; j++) wmma::fill_fragment(acc[i][j], 0.f);

    auto cpA = [&](int stage, int k0) {
        unsigned d = sA + (unsigned)(stage * BM * LDA_S + a_r * LDA_S + a_c) * 2;
        cp16z(d, abase0 + k0 + a_c, tk0 >= 0);
        cp16z(d + 64 * LDA_S * 2, abase1 + k0 + a_c, tk1 >= 0);
    };
    auto ldgB = [&](Breg& r, int k0) {
        const float* p0 = &B[(size_t)(k0 + b_r) * 1024 + n0 + b_c];
        r.a0 = *(const float4*)p0; r.a1 = *(const float4*)(p0 + 4);
        const float* p1 = &B[(size_t)(k0 + b_r + 16) * 1024 + n0 + b_c];
        r.b0 = *(const float4*)p1; r.b1 = *(const float4*)(p1 + 4);
    };
    auto stsB = [&](const Breg& r, int buf) {
        *(uint4*)&Bs[buf][b_r * LDB_S + b_c] = f8_to_bf8(r.a0, r.a1);
        *(uint4*)&Bs[buf][(b_r + 16) * LDB_S + b_c] = f8_to_bf8(r.b0, r.b1);
    };

    const int n = HID / BK;
    Breg r0, r1;
    cpA(0, 0); CP_COMMIT();
    cpA(1, BK); CP_COMMIT();
    ldgB(r0, 0); ldgB(r1, BK);
    stsB(r0, 0);
    ldgB(r0, 2 * BK);
    cp_wait<1>(); __syncthreads();

    for (int it = 0; it < n; it++) {
        mma_tile(As[it & 1], Bs[it & 1], acc, wm, wn);
        if (it + 1 < n) {
            Breg& rr = (it & 1) ? r0 : r1;
            stsB(rr, (it + 1) & 1);
            if (it + 3 < n) ldgB(rr, (it + 3) * BK);
            cp_wait<0>();
            __syncthreads();
            if (it + 2 < n) { cpA(it & 1, (it + 2) * BK); CP_COMMIT(); }
        }
    }
#pragma unroll
    for (int i = 0; i < 2; i++)
#pragma unroll
        for (int j = 0; j < 4; j++)
            wmma::store_matrix_sync(
                g_gu + (size_t)(off + m0 + wm * 32 + i * 16) * 1024 + n0 + wn * 64 + j * 16,
                acc[i][j], 1024, wmma::mem_row_major);
}

// act[row,i] = silu(g)*u*w -> bf16
__global__ void k_moe_act() {
    int idx = blockIdx.x * 256 + threadIdx.x;
    int r  = idx >> 7;
    if (r >= g_total) return;
    int i4 = (idx & 127) * 4;
    float4 g = *(const float4*)&g_gu[(size_t)r * 1024 + i4];
    float4 u = *(const float4*)&g_gu[(size_t)r * 1024 + 512 + i4];
    float w = g_w[r];
    float s0 = g.x / (1.f + __expf(-g.x)) * u.x * w;
    float s1 = g.y / (1.f + __expf(-g.y)) * u.y * w;
    float s2 = g.z / (1.f + __expf(-g.z)) * u.z * w;
    float s3 = g.w / (1.f + __expf(-g.w)) * u.w * w;
    __nv_bfloat162 p0 = __floats2bfloat162_rn(s0, s1);
    __nv_bfloat162 p1 = __floats2bfloat162_rn(s2, s3);
    uint2 v;
    v.x = *reinterpret_cast<unsigned*>(&p0);
    v.y = *reinterpret_cast<unsigned*>(&p1);
    *(uint2*)&g_actb[(size_t)r * INTER + i4] = v;
}

// ---------------------------------------------------------------------------
// MoE GEMM 2 (bf16, pipelined) with staged scatter-add
// ---------------------------------------------------------------------------
__global__ void __launch_bounds__(256) k_moe2(const float* __restrict__ Wd,
                                              float* __restrict__ out) {
    int e = blockIdx.z;
    int cnt = g_cnt[e];
    int m0 = blockIdx.y * BM;
    if (m0 >= cnt) return;
    int off = g_off[e];
    int n0 = blockIdx.x * BN;
    const float* B = Wd + (size_t)e * (INTER * HID);

    __shared__ __nv_bfloat16 As[2][BM * LDA_S];
    __shared__ __nv_bfloat16 Bs[2][BK * LDB_S];
    __shared__ float stage_s[8 * 272];
    __shared__ int stok[BM];
    int tid = threadIdx.x;
    int lane = tid & 31;
    int warp = tid >> 5;
    int wm = warp & 3, wn = warp >> 2;
    if (tid < BM) stok[tid] = (m0 + tid < cnt) ? g_tok[off + m0 + tid] : -1;
    __syncthreads();

    int a_r = tid >> 2, a_c = (tid & 3) * 8;
    int b_r = tid >> 4, b_c = (tid & 15) * 8;
    unsigned sA = (unsigned)__cvta_generic_to_shared(&As[0][0]);
    const __nv_bfloat16* Ap = g_actb + (size_t)(off + m0) * INTER;

    FragC acc[2][4];
#pragma unroll
    for (int i = 0; i < 2; i++)
#pragma unroll
        for (int j = 0; j < 4; j++) wmma::fill_fragment(acc[i][j], 0.f);

    auto cpA = [&](int stage, int k0) {
        unsigned d = sA + (unsigned)(stage * BM * LDA_S + a_r * LDA_S + a_c) * 2;
        cp16(d, Ap + (size_t)a_r * INTER + k0 + a_c);
        cp16(d + 64 * LDA_S * 2, Ap + (size_t)(a_r + 64) * INTER + k0 + a_c);
    };
    auto ldgB = [&](Breg& r, int k0) {
        const float* p0 = &B[(size_t)(k0 + b_r) * HID + n0 + b_c];
        r.a0 = *(const float4*)p0; r.a1 = *(const float4*)(p0 + 4);
        const float* p1 = &B[(size_t)(k0 + b_r + 16) * HID + n0 + b_c];
        r.b0 = *(const float4*)p1; r.b1 = *(const float4*)(p1 + 4);
    };
    auto stsB = [&](const Breg& r, int buf) {
        *(uint4*)&Bs[buf][b_r * LDB_S + b_c] = f8_to_bf8(r.a0, r.a1);
        *(uint4*)&Bs[buf][(b_r + 16) * LDB_S + b_c] = f8_to_bf8(r.b0, r.b1);
    };

    const int n = INTER / BK;
    Breg r0, r1;
    cpA(0, 0); CP_COMMIT();
    cpA(1, BK); CP_COMMIT();
    ldgB(r0, 0); ldgB(r1, BK);
    stsB(r0, 0);
    ldgB(r0, 2 * BK);
    cp_wait<1>(); __syncthreads();

    for (int it = 0; it < n; it++) {
        mma_tile(As[it & 1], Bs[it & 1], acc, wm, wn);
        if (it + 1 < n) {
            Breg& rr = (it & 1) ? r0 : r1;
            stsB(rr, (it + 1) & 1);
            if (it + 3 < n) ldgB(rr, (it + 3) * BK);
            cp_wait<0>();
            __syncthreads();
            if (it + 2 < n) { cpA(it & 1, (it + 2) * BK); CP_COMMIT(); }
        }
    }

#pragma unroll
    for (int i = 0; i < 2; i++) {
#pragma unroll
        for (int j = 0; j < 4; j++) {
            wmma::store_matrix_sync(&stage_s[warp * 272], acc[i][j], 16, wmma::mem_row_major);
            __syncwarp();
#pragma unroll
            for (int q = 0; q < 8; q++) {
                int el = lane + q * 32;
                int r = el >> 4, c = el & 15;
                int lr = wm * 32 + i * 16 + r;
                if (m0 + lr < cnt) {
                    int tk = stok[lr];
                    atomicAdd(&out[(size_t)tk * HID + n0 + wn * 64 + j * 16 + c],
                              stage_s[warp * 272 + r * 16 + c]);
                }
            }
            __syncwarp();
        }
    }
}

// ---------------------------------------------------------------------------
// Launch
// ---------------------------------------------------------------------------
extern "C" void kernel_launch(void* const* d_in, const int* in_sizes, int n_in,
                              void* d_out, int out_size) {
    const int*   positions = (const int*)  d_in[0];
    const float* hidden    = (const float*)d_in[1];
    const float* Wqkv      = (const float*)d_in[2];
    const float* Wo        = (const float*)d_in[3];
    const float* qnw       = (const float*)d_in[4];
    const float* knw       = (const float*)d_in[5];
    const float* inln      = (const float*)d_in[6];
    const float* postln    = (const float*)d_in[7];
    const float* Wg        = (const float*)d_in[8];
    const float* Wgu       = (const float*)d_in[9];
    const float* Wd        = (const float*)d_in[10];
    float* out = (float*)d_out;

    __nv_bfloat16 *p_hb, *p_attnb, *p_h2b;
    float *p_qkv, *p_h2;
    cudaGetSymbolAddress((void**)&p_hb,    g_hb);
    cudaGetSymbolAddress((void**)&p_qkv,   g_qkv);
    cudaGetSymbolAddress((void**)&p_h2,    g_h2);
    cudaGetSymbolAddress((void**)&p_h2b,   g_h2b);
    cudaGetSymbolAddress((void**)&p_attnb, g_attnb);

    const int ATTN_SMEM = (4 * 64 * LDH) * 2 + (2 * 64 * LDF) * 4 + (64 + 64 + 128 + 128) * 4;
    cudaFuncSetAttribute(k_attn_wmma, cudaFuncAttributeMaxDynamicSharedMemorySize, ATTN_SMEM);

    k_rmsnorm<<<T_TOK, 256>>>(hidden, inln, nullptr, p_hb);
    k_gemm_bf16<<<dim3(QKV_N / BN, T_TOK / BM), 256>>>(p_hb, Wqkv, p_qkv, nullptr,
                                                       T_TOK, QKV_N, HID);
    k_qk_prep<<<dim3(NH + 2 * NKV, T_TOK), 32>>>(positions, qnw, knw);
    k_attn_wmma<<<dim3(T_TOK / 64, NH), 128, ATTN_SMEM>>>();
    k_gemm_bf16<<<dim3(HID / BN, T_TOK / BM), 256>>>(p_attnb, Wo, out, hidden,
                                                     T_TOK, HID, NH * HD);
    k_rmsnorm<<<T_TOK, 256>>>(out, postln, p_h2, p_h2b);
    k_zero<<<1, 64>>>();
    k_route<<<T_TOK, 64>>>(p_h2, Wg);
    k_scan<<<1, 1>>>();
    k_scatter<<<T_TOK, 8>>>();
    k_moe1<<<dim3(1024 / BN, 8, NE), 256>>>(p_h2b, Wgu);
    k_moe_act<<<(NA_PAD * 128) / 256, 256>>>();
    k_moe2<<<dim3(HID / BN, 8, NE), 256>>>(Wd, out);
}

// round 6
// speedup vs baseline: 1.5626x; 1.5626x over previous
#include <cuda_runtime.h>
#include <cuda_bf16.h>
#include <mma.h>
#include <math.h>

using namespace nvcuda;

// ---------------------------------------------------------------------------
// Problem constants
// ---------------------------------------------------------------------------
#define T_TOK  1024
#define HID    1024
#define NH     16
#define NKV    4
#define HD     64
#define QKV_N  1536
#define NE     64
#define NG     8
#define INTER  512
#define NA     (T_TOK*NG)
#define NA_PAD 16384

// GEMM tiling
#define BM 128
#define BN 128
#define BK 32
#define LDA_S 40
#define LDB_S 136

// attention smem leading dim (bf16): stride 144B -> conflict-free ldmatrix
#define LDH 72

// ---------------------------------------------------------------------------
// Scratch (static device globals)
// ---------------------------------------------------------------------------
__device__ __nv_bfloat16 g_hb   [T_TOK*HID];
__device__ float         g_qkv  [T_TOK*QKV_N];
__device__ __nv_bfloat16 g_qb   [T_TOK*NH*HD];
__device__ __nv_bfloat16 g_kb   [T_TOK*NKV*HD];
__device__ __nv_bfloat16 g_vb   [T_TOK*NKV*HD];
__device__ __nv_bfloat16 g_attnb[T_TOK*NH*HD];
__device__ float         g_h2   [T_TOK*HID];
__device__ __nv_bfloat16 g_h2b  [T_TOK*HID];
__device__ float         g_gu   [NA_PAD*1024];
__device__ __nv_bfloat16 g_actb [NA_PAD*INTER];
__device__ int   g_cnt [NE];
__device__ int   g_off [NE];
__device__ int   g_fill[NE];
__device__ int   g_total;
__device__ int   g_selid[NA];
__device__ float g_selw [NA];
__device__ int   g_tok  [NA_PAD];
__device__ float g_w    [NA_PAD];

// ---------------------------------------------------------------------------
// WMMA types (GEMMs) + helpers
// ---------------------------------------------------------------------------
using FragA  = wmma::fragment<wmma::matrix_a, 16, 16, 16, __nv_bfloat16, wmma::row_major>;
using FragB  = wmma::fragment<wmma::matrix_b, 16, 16, 16, __nv_bfloat16, wmma::row_major>;
using FragC  = wmma::fragment<wmma::accumulator, 16, 16, 16, float>;

__device__ __forceinline__ uint4 f8_to_bf8(float4 a, float4 b) {
    __nv_bfloat162 p0 = __floats2bfloat162_rn(a.x, a.y);
    __nv_bfloat162 p1 = __floats2bfloat162_rn(a.z, a.w);
    __nv_bfloat162 p2 = __floats2bfloat162_rn(b.x, b.y);
    __nv_bfloat162 p3 = __floats2bfloat162_rn(b.z, b.w);
    uint4 r;
    r.x = *reinterpret_cast<unsigned*>(&p0);
    r.y = *reinterpret_cast<unsigned*>(&p1);
    r.z = *reinterpret_cast<unsigned*>(&p2);
    r.w = *reinterpret_cast<unsigned*>(&p3);
    return r;
}

__device__ __forceinline__ void mma_tile(const __nv_bfloat16* As, const __nv_bfloat16* Bs,
                                         FragC (&acc)[2][4], int wm, int wn) {
#pragma unroll
    for (int kk = 0; kk < BK; kk += 16) {
        FragA a[2];
        FragB b[4];
#pragma unroll
        for (int i = 0; i < 2; i++)
            wmma::load_matrix_sync(a[i], As + (wm * 32 + i * 16) * LDA_S + kk, LDA_S);
#pragma unroll
        for (int j = 0; j < 4; j++)
            wmma::load_matrix_sync(b[j], Bs + kk * LDB_S + wn * 64 + j * 16, LDB_S);
#pragma unroll
        for (int i = 0; i < 2; i++)
#pragma unroll
            for (int j = 0; j < 4; j++)
                wmma::mma_sync(acc[i][j], a[i], b[j], acc[i][j]);
    }
}

// raw PTX mma/ldmatrix for attention
__device__ __forceinline__ void mma16816(float c[4], const unsigned a[4],
                                         unsigned b0, unsigned b1) {
    asm volatile(
        "mma.sync.aligned.m16n8k16.row.col.f32.bf16.bf16.f32 "
        "{%0,%1,%2,%3}, {%4,%5,%6,%7}, {%8,%9}, {%0,%1,%2,%3};\n"
        : "+f"(c[0]), "+f"(c[1]), "+f"(c[2]), "+f"(c[3])
        : "r"(a[0]), "r"(a[1]), "r"(a[2]), "r"(a[3]), "r"(b0), "r"(b1));
}
__device__ __forceinline__ void ldsm4(unsigned d[4], unsigned addr) {
    asm volatile("ldmatrix.sync.aligned.m8n8.x4.shared.b16 {%0,%1,%2,%3}, [%4];\n"
        : "=r"(d[0]), "=r"(d[1]), "=r"(d[2]), "=r"(d[3]) : "r"(addr));
}
__device__ __forceinline__ void ldsm4t(unsigned d[4], unsigned addr) {
    asm volatile("ldmatrix.sync.aligned.m8n8.x4.trans.shared.b16 {%0,%1,%2,%3}, [%4];\n"
        : "=r"(d[0]), "=r"(d[1]), "=r"(d[2]), "=r"(d[3]) : "r"(addr));
}

// ---------------------------------------------------------------------------
// RMSNorm
// ---------------------------------------------------------------------------
__global__ void k_rmsnorm(const float* __restrict__ in,
                          const float* __restrict__ w,
                          float* __restrict__ outf,
                          __nv_bfloat16* __restrict__ outb) {
    int t = blockIdx.x;
    const float* x = in + (size_t)t * HID;
    float ss = 0.f;
    for (int i = threadIdx.x; i < HID; i += 256) { float v = x[i]; ss += v * v; }
#pragma unroll
    for (int o = 16; o; o >>= 1) ss += __shfl_xor_sync(0xffffffffu, ss, o);
    __shared__ float red[8];
    __shared__ float stot;
    if ((threadIdx.x & 31) == 0) red[threadIdx.x >> 5] = ss;
    __syncthreads();
    if (threadIdx.x == 0) {
        float s = 0.f;
#pragma unroll
        for (int i = 0; i < 8; i++) s += red[i];
        stot = rsqrtf(s * (1.f / HID) + 1e-6f);
    }
    __syncthreads();
    float sc = stot;
    for (int i = threadIdx.x; i < HID; i += 256) {
        float v = x[i] * sc * w[i];
        if (outf) outf[(size_t)t * HID + i] = v;
        if (outb) outb[(size_t)t * HID + i] = __float2bfloat16(v);
    }
}

// ---------------------------------------------------------------------------
// Dense bf16 GEMM (round-4 version: single reg prefetch, double smem buffer)
// ---------------------------------------------------------------------------
__global__ void __launch_bounds__(256) k_gemm_bf16(
        const __nv_bfloat16* __restrict__ A, const float* __restrict__ B,
        float* __restrict__ C, const float* __restrict__ R,
        int M, int N, int K) {
    __shared__ __nv_bfloat16 As[2][BM * LDA_S];
    __shared__ __nv_bfloat16 Bs[2][BK * LDB_S];
    int tid = threadIdx.x;
    int warp = tid >> 5;
    int wm = warp & 3, wn = warp >> 2;
    int m0 = blockIdx.y * BM, n0 = blockIdx.x * BN;

    int a_r = tid >> 2, a_c = (tid & 3) * 8;
    int b_r = tid >> 4, b_c = (tid & 15) * 8;

    FragC acc[2][4];
    if (R) {
#pragma unroll
        for (int i = 0; i < 2; i++)
#pragma unroll
            for (int j = 0; j < 4; j++)
                wmma::load_matrix_sync(acc[i][j],
                    R + (size_t)(m0 + wm * 32 + i * 16) * N + n0 + wn * 64 + j * 16,
                    N, wmma::mem_row_major);
    } else {
#pragma unroll
        for (int i = 0; i < 2; i++)
#pragma unroll
            for (int j = 0; j < 4; j++) wmma::fill_fragment(acc[i][j], 0.f);
    }

    uint4 ra0, ra1;
    float4 rb0a, rb0b, rb1a, rb1b;
    auto ldg = [&](int k0) {
        ra0 = *(const uint4*)&A[(size_t)(m0 + a_r) * K + k0 + a_c];
        ra1 = *(const uint4*)&A[(size_t)(m0 + a_r + 64) * K + k0 + a_c];
        const float* p0 = &B[(size_t)(k0 + b_r) * N + n0 + b_c];
        rb0a = *(const float4*)p0; rb0b = *(const float4*)(p0 + 4);
        const float* p1 = &B[(size_t)(k0 + b_r + 16) * N + n0 + b_c];
        rb1a = *(const float4*)p1; rb1b = *(const float4*)(p1 + 4);
    };
    auto sts = [&](int buf) {
        *(uint4*)&As[buf][a_r * LDA_S + a_c] = ra0;
        *(uint4*)&As[buf][(a_r + 64) * LDA_S + a_c] = ra1;
        *(uint4*)&Bs[buf][b_r * LDB_S + b_c] = f8_to_bf8(rb0a, rb0b);
        *(uint4*)&Bs[buf][(b_r + 16) * LDB_S + b_c] = f8_to_bf8(rb1a, rb1b);
    };

    int niter = K / BK;
    ldg(0); sts(0); __syncthreads();
    for (int it = 0; it < niter; it++) {
        if (it + 1 < niter) ldg((it + 1) * BK);
        mma_tile(As[it & 1], Bs[it & 1], acc, wm, wn);
        if (it + 1 < niter) { sts((it + 1) & 1); __syncthreads(); }
    }
#pragma unroll
    for (int i = 0; i < 2; i++)
#pragma unroll
        for (int j = 0; j < 4; j++)
            wmma::store_matrix_sync(
                C + (size_t)(m0 + wm * 32 + i * 16) * N + n0 + wn * 64 + j * 16,
                acc[i][j], N, wmma::mem_row_major);
}

// ---------------------------------------------------------------------------
// Per-head RMSNorm + RoPE (q,k) and copy (v) -> bf16
// ---------------------------------------------------------------------------
__global__ void k_qk_prep(const int* __restrict__ pos,
                          const float* __restrict__ qnw,
                          const float* __restrict__ knw) {
    int hh = blockIdx.x;
    int t  = blockIdx.y;
    int i  = threadIdx.x;
    if (hh >= NH + NKV) {
        int vh = hh - NH - NKV;
        const float* src = g_qkv + (size_t)t * QKV_N + (NH + NKV) * HD + vh * HD;
        __nv_bfloat16* dst = g_vb + (size_t)t * (NKV * HD) + vh * HD;
        dst[i]      = __float2bfloat16(src[i]);
        dst[i + 32] = __float2bfloat16(src[i + 32]);
        return;
    }
    const float* src; __nv_bfloat16* dst; const float* w;
    if (hh < NH) {
        src = g_qkv + (size_t)t * QKV_N + hh * HD;
        dst = g_qb  + (size_t)t * (NH * HD) + hh * HD;
        w = qnw;
    } else {
        int kh = hh - NH;
        src = g_qkv + (size_t)t * QKV_N + NH * HD + kh * HD;
        dst = g_kb  + (size_t)t * (NKV * HD) + kh * HD;
        w = knw;
    }
    float x1 = src[i], x2 = src[i + 32];
    float ss = x1 * x1 + x2 * x2;
#pragma unroll
    for (int o = 16; o; o >>= 1) ss += __shfl_xor_sync(0xffffffffu, ss, o);
    float sc = rsqrtf(ss * (1.f / 64.f) + 1e-6f);
    x1 *= sc * w[i];
    x2 *= sc * w[i + 32];
    float p = (float)pos[t];
    float inv = powf(10000.f, -(float)i * (1.f / 32.f));
    float f = p * inv;
    float c = cosf(f), s = sinf(f);
    dst[i]      = __float2bfloat16(x1 * c - x2 * s);
    dst[i + 32] = __float2bfloat16(x2 * c + x1 * s);
}

// ---------------------------------------------------------------------------
// Flash attention: register-resident FA2 with mma.m16n8k16 + ldmatrix.
// grid (16 qtiles, 16 heads), 128 threads. Warp w owns q rows [w*16, w*16+16).
// ---------------------------------------------------------------------------
__global__ void __launch_bounds__(128) k_attn_mma() {
    __shared__ __nv_bfloat16 Qs[64 * LDH];
    __shared__ __nv_bfloat16 Ks[64 * LDH];
    __shared__ __nv_bfloat16 Vs[64 * LDH];
    int h = blockIdx.y, qt = blockIdx.x;
    int m0 = qt * 64, kvh = h >> 2;
    int tid = threadIdx.x, warp = tid >> 5, lane = tid & 31;
    int g = lane >> 3, li = lane & 7;

    // load Q tile
#pragma unroll
    for (int j = 0; j < 4; j++) {
        int idx = tid + j * 128;
        int r = idx >> 3, c = (idx & 7) * 8;
        *(uint4*)&Qs[r * LDH + c] =
            *(const uint4*)&g_qb[(size_t)(m0 + r) * (NH * HD) + h * HD + c];
    }
    __syncthreads();

    // Q A-fragments (persist across kv loop): qa[hd chunk][4]
    unsigned qa[4][4];
    {
        int row = warp * 16 + (g & 1) * 8 + li;
        int colg = (g >> 1) * 8;
#pragma unroll
        for (int hc = 0; hc < 4; hc++)
            ldsm4(qa[hc], (unsigned)__cvta_generic_to_shared(&Qs[row * LDH + hc * 16 + colg]));
    }

    float o[8][4];
#pragma unroll
    for (int f = 0; f < 8; f++) { o[f][0] = o[f][1] = o[f][2] = o[f][3] = 0.f; }
    float mr0 = -INFINITY, mr1 = -INFINITY, l0 = 0.f, l1 = 0.f;
    int R0 = m0 + warp * 16 + (lane >> 2);
    int R1 = R0 + 8;

    for (int nt = 0; nt <= qt; nt++) {
        int n0 = nt * 64;
        __syncthreads();
#pragma unroll
        for (int j = 0; j < 4; j++) {
            int idx = tid + j * 128;
            int r = idx >> 3, c = (idx & 7) * 8;
            *(uint4*)&Ks[r * LDH + c] =
                *(const uint4*)&g_kb[(size_t)(n0 + r) * (NKV * HD) + kvh * HD + c];
            *(uint4*)&Vs[r * LDH + c] =
                *(const uint4*)&g_vb[(size_t)(n0 + r) * (NKV * HD) + kvh * HD + c];
        }
        __syncthreads();

        // S = Q @ K^T : 8 m16n8 accumulators
        float s[8][4];
#pragma unroll
        for (int f = 0; f < 8; f++) { s[f][0] = s[f][1] = s[f][2] = s[f][3] = 0.f; }
#pragma unroll
        for (int hc = 0; hc < 4; hc++) {
#pragma unroll
            for (int ng = 0; ng < 4; ng++) {
                unsigned d[4];
                int row = ng * 16 + (g >> 1) * 8 + li;
                int col = hc * 16 + (g & 1) * 8;
                ldsm4(d, (unsigned)__cvta_generic_to_shared(&Ks[row * LDH + col]));
                mma16816(s[2 * ng],     qa[hc], d[0], d[1]);
                mma16816(s[2 * ng + 1], qa[hc], d[2], d[3]);
            }
        }

        // register softmax (rows R0, R1 per thread; quad-lane reductions)
        bool diag = (nt == qt);
        float mx0 = -INFINITY, mx1 = -INFINITY;
#pragma unroll
        for (int f = 0; f < 8; f++) {
            int cb = n0 + f * 8 + (lane & 3) * 2;
            s[f][0] *= 0.125f; s[f][1] *= 0.125f;
            s[f][2] *= 0.125f; s[f][3] *= 0.125f;
            if (diag) {
                if (cb     > R0) s[f][0] = -INFINITY;
                if (cb + 1 > R0) s[f][1] = -INFINITY;
                if (cb     > R1) s[f][2] = -INFINITY;
                if (cb + 1 > R1) s[f][3] = -INFINITY;
            }
            mx0 = fmaxf(mx0, fmaxf(s[f][0], s[f][1]));
            mx1 = fmaxf(mx1, fmaxf(s[f][2], s[f][3]));
        }
        mx0 = fmaxf(mx0, __shfl_xor_sync(0xffffffffu, mx0, 1));
        mx0 = fmaxf(mx0, __shfl_xor_sync(0xffffffffu, mx0, 2));
        mx1 = fmaxf(mx1, __shfl_xor_sync(0xffffffffu, mx1, 1));
        mx1 = fmaxf(mx1, __shfl_xor_sync(0xffffffffu, mx1, 2));
        float mn0 = fmaxf(mr0, mx0), mn1 = fmaxf(mr1, mx1);
        float al0 = __expf(mr0 - mn0), al1 = __expf(mr1 - mn1);
        mr0 = mn0; mr1 = mn1;

        unsigned P[4][4];   // A-fragments of P per kv16 chunk
        float ps0 = 0.f, ps1 = 0.f;
#pragma unroll
        for (int f = 0; f < 8; f++) {
            float p0 = __expf(s[f][0] - mn0);
            float p1 = __expf(s[f][1] - mn0);
            float p2 = __expf(s[f][2] - mn1);
            float p3 = __expf(s[f][3] - mn1);
            ps0 += p0 + p1; ps1 += p2 + p3;
            __nv_bfloat162 b0 = __floats2bfloat162_rn(p0, p1);
            __nv_bfloat162 b1 = __floats2bfloat162_rn(p2, p3);
            P[f >> 1][(f & 1) * 2]     = *reinterpret_cast<unsigned*>(&b0);
            P[f >> 1][(f & 1) * 2 + 1] = *reinterpret_cast<unsigned*>(&b1);
        }
        ps0 += __shfl_xor_sync(0xffffffffu, ps0, 1);
        ps0 += __shfl_xor_sync(0xffffffffu, ps0, 2);
        ps1 += __shfl_xor_sync(0xffffffffu, ps1, 1);
        ps1 += __shfl_xor_sync(0xffffffffu, ps1, 2);
        l0 = l0 * al0 + ps0;
        l1 = l1 * al1 + ps1;
#pragma unroll
        for (int f = 0; f < 8; f++) {
            o[f][0] *= al0; o[f][1] *= al0;
            o[f][2] *= al1; o[f][3] *= al1;
        }

        // O += P @ V
#pragma unroll
        for (int c = 0; c < 4; c++) {
#pragma unroll
            for (int j = 0; j < 4; j++) {
                unsigned d[4];
                int row = c * 16 + (g & 1) * 8 + li;
                int col = j * 16 + (g >> 1) * 8;
                ldsm4t(d, (unsigned)__cvta_generic_to_shared(&Vs[row * LDH + col]));
                mma16816(o[2 * j],     P[c], d[0], d[1]);
                mma16816(o[2 * j + 1], P[c], d[2], d[3]);
            }
        }
    }

    // epilogue: normalize, store bf16 pairs
    float i0 = 1.f / l0, i1 = 1.f / l1;
#pragma unroll
    for (int f = 0; f < 8; f++) {
        int col = h * HD + f * 8 + (lane & 3) * 2;
        __nv_bfloat162 v0 = __floats2bfloat162_rn(o[f][0] * i0, o[f][1] * i0);
        __nv_bfloat162 v1 = __floats2bfloat162_rn(o[f][2] * i1, o[f][3] * i1);
        *(unsigned*)&g_attnb[(size_t)R0 * (NH * HD) + col] = *reinterpret_cast<unsigned*>(&v0);
        *(unsigned*)&g_attnb[(size_t)R1 * (NH * HD) + col] = *reinterpret_cast<unsigned*>(&v1);
    }
}

// ---------------------------------------------------------------------------
// Routing
// ---------------------------------------------------------------------------
__global__ void k_zero() {
    int i = threadIdx.x;
    if (i < NE) { g_cnt[i] = 0; g_fill[i] = 0; }
}

__global__ void k_route(const float* __restrict__ H2, const float* __restrict__ Wg) {
    int t = blockIdx.x;
    int e = threadIdx.x;
    __shared__ float sh[HID];
    for (int i = e; i < HID; i += 64) sh[i] = H2[(size_t)t * HID + i];
    __syncthreads();
    float a0 = 0, a1 = 0, a2 = 0, a3 = 0;
    for (int k = 0; k < HID; k += 4) {
        a0 += sh[k]     * Wg[(size_t)k       * NE + e];
        a1 += sh[k + 1] * Wg[(size_t)(k + 1) * NE + e];
        a2 += sh[k + 2] * Wg[(size_t)(k + 2) * NE + e];
        a3 += sh[k + 3] * Wg[(size_t)(k + 3) * NE + e];
    }
    __shared__ float logits[NE];
    logits[e] = (a0 + a1) + (a2 + a3);
    __syncthreads();
    if (e == 0) {
        float sv[NG]; int si[NG];
#pragma unroll
        for (int gg = 0; gg < NG; gg++) {
            float best = logits[gg * 8]; int bi = gg * 8;
#pragma unroll
            for (int j = 1; j < 8; j++) {
                float v = logits[gg * 8 + j];
                if (v > best) { best = v; bi = gg * 8 + j; }
            }
            sv[gg] = best; si[gg] = bi;
        }
        float m = sv[0];
#pragma unroll
        for (int gg = 1; gg < NG; gg++) m = fmaxf(m, sv[gg]);
        float sum = 0.f, p[NG];
#pragma unroll
        for (int gg = 0; gg < NG; gg++) { p[gg] = expf(sv[gg] - m); sum += p[gg]; }
        float is = 1.f / sum;
#pragma unroll
        for (int gg = 0; gg < NG; gg++) {
            g_selid[t * NG + gg] = si[gg];
            g_selw [t * NG + gg] = p[gg] * is;
            atomicAdd(&g_cnt[si[gg]], 1);
        }
    }
}

__global__ void k_scan() {
    int s = 0;
    for (int e = 0; e < NE; e++) { g_off[e] = s; s += (g_cnt[e] + BM - 1) & ~(BM - 1); }
    g_total = s;
}

__global__ void k_scatter() {
    int t = blockIdx.x, gg = threadIdx.x;
    int e = g_selid[t * NG + gg];
    int slot = atomicAdd(&g_fill[e], 1);
    int row = g_off[e] + slot;
    g_tok[row] = t;
    g_w[row]   = g_selw[t * NG + gg];
}

// ---------------------------------------------------------------------------
// MoE GEMM 1 (round-4 version)
// ---------------------------------------------------------------------------
__global__ void __launch_bounds__(256) k_moe1(const __nv_bfloat16* __restrict__ Ab,
                                              const float* __restrict__ Wgu) {
    int e = blockIdx.z;
    int cnt = g_cnt[e];
    int m0 = blockIdx.y * BM;
    if (m0 >= cnt) return;
    int off = g_off[e];
    int n0 = blockIdx.x * BN;
    const float* B = Wgu + (size_t)e * (HID * 1024);

    __shared__ __nv_bfloat16 As[2][BM * LDA_S];
    __shared__ __nv_bfloat16 Bs[2][BK * LDB_S];
    __shared__ int stok[BM];
    int tid = threadIdx.x;
    int warp = tid >> 5;
    int wm = warp & 3, wn = warp >> 2;
    if (tid < BM) stok[tid] = (m0 + tid < cnt) ? g_tok[off + m0 + tid] : -1;
    __syncthreads();

    int a_r = tid >> 2, a_c = (tid & 3) * 8;
    int b_r = tid >> 4, b_c = (tid & 15) * 8;
    int tk0 = stok[a_r], tk1 = stok[a_r + 64];

    FragC acc[2][4];
#pragma unroll
    for (int i = 0; i < 2; i++)
#pragma unroll
        for (int j = 0; j < 4; j++) wmma::fill_fragment(acc[i][j], 0.f);

    uint4 ra0, ra1;
    float4 rb0a, rb0b, rb1a, rb1b;
    const uint4 Z = make_uint4(0, 0, 0, 0);
    auto ldg = [&](int k0) {
        ra0 = (tk0 >= 0) ? *(const uint4*)&Ab[(size_t)tk0 * HID + k0 + a_c] : Z;
        ra1 = (tk1 >= 0) ? *(const uint4*)&Ab[(size_t)tk1 * HID + k0 + a_c] : Z;
        const float* p0 = &B[(size_t)(k0 + b_r) * 1024 + n0 + b_c];
        rb0a = *(const float4*)p0; rb0b = *(const float4*)(p0 + 4);
        const float* p1 = &B[(size_t)(k0 + b_r + 16) * 1024 + n0 + b_c];
        rb1a = *(const float4*)p1; rb1b = *(const float4*)(p1 + 4);
    };
    auto sts = [&](int buf) {
        *(uint4*)&As[buf][a_r * LDA_S + a_c] = ra0;
        *(uint4*)&As[buf][(a_r + 64) * LDA_S + a_c] = ra1;
        *(uint4*)&Bs[buf][b_r * LDB_S + b_c] = f8_to_bf8(rb0a, rb0b);
        *(uint4*)&Bs[buf][(b_r + 16) * LDB_S + b_c] = f8_to_bf8(rb1a, rb1b);
    };

    const int niter = HID / BK;
    ldg(0); sts(0); __syncthreads();
    for (int it = 0; it < niter; it++) {
        if (it + 1 < niter) ldg((it + 1) * BK);
        mma_tile(As[it & 1], Bs[it & 1], acc, wm, wn);
        if (it + 1 < niter) { sts((it + 1) & 1); __syncthreads(); }
    }
#pragma unroll
    for (int i = 0; i < 2; i++)
#pragma unroll
        for (int j = 0; j < 4; j++)
            wmma::store_matrix_sync(
                g_gu + (size_t)(off + m0 + wm * 32 + i * 16) * 1024 + n0 + wn * 64 + j * 16,
                acc[i][j], 1024, wmma::mem_row_major);
}

// act[row,i] = silu(g)*u*w -> bf16
__global__ void k_moe_act() {
    int idx = blockIdx.x * 256 + threadIdx.x;
    int r  = idx >> 7;
    if (r >= g_total) return;
    int i4 = (idx & 127) * 4;
    float4 g = *(const float4*)&g_gu[(size_t)r * 1024 + i4];
    float4 u = *(const float4*)&g_gu[(size_t)r * 1024 + 512 + i4];
    float w = g_w[r];
    float s0 = g.x / (1.f + __expf(-g.x)) * u.x * w;
    float s1 = g.y / (1.f + __expf(-g.y)) * u.y * w;
    float s2 = g.z / (1.f + __expf(-g.z)) * u.z * w;
    float s3 = g.w / (1.f + __expf(-g.w)) * u.w * w;
    __nv_bfloat162 p0 = __floats2bfloat162_rn(s0, s1);
    __nv_bfloat162 p1 = __floats2bfloat162_rn(s2, s3);
    uint2 v;
    v.x = *reinterpret_cast<unsigned*>(&p0);
    v.y = *reinterpret_cast<unsigned*>(&p1);
    *(uint2*)&g_actb[(size_t)r * INTER + i4] = v;
}

// ---------------------------------------------------------------------------
// MoE GEMM 2 (round-4 version) with staged scatter-add
// ---------------------------------------------------------------------------
__global__ void __launch_bounds__(256) k_moe2(const float* __restrict__ Wd,
                                              float* __restrict__ out) {
    int e = blockIdx.z;
    int cnt = g_cnt[e];
    int m0 = blockIdx.y * BM;
    if (m0 >= cnt) return;
    int off = g_off[e];
    int n0 = blockIdx.x * BN;
    const float* B = Wd + (size_t)e * (INTER * HID);

    __shared__ __nv_bfloat16 As[2][BM * LDA_S];
    __shared__ __nv_bfloat16 Bs[2][BK * LDB_S];
    __shared__ float stage_s[8 * 272];
    __shared__ int stok[BM];
    int tid = threadIdx.x;
    int lane = tid & 31;
    int warp = tid >> 5;
    int wm = warp & 3, wn = warp >> 2;
    if (tid < BM) stok[tid] = (m0 + tid < cnt) ? g_tok[off + m0 + tid] : -1;
    __syncthreads();

    int a_r = tid >> 2, a_c = (tid & 3) * 8;
    int b_r = tid >> 4, b_c = (tid & 15) * 8;

    FragC acc[2][4];
#pragma unroll
    for (int i = 0; i < 2; i++)
#pragma unroll
        for (int j = 0; j < 4; j++) wmma::fill_fragment(acc[i][j], 0.f);

    uint4 ra0, ra1;
    float4 rb0a, rb0b, rb1a, rb1b;
    auto ldg = [&](int k0) {
        ra0 = *(const uint4*)&g_actb[(size_t)(off + m0 + a_r) * INTER + k0 + a_c];
        ra1 = *(const uint4*)&g_actb[(size_t)(off + m0 + a_r + 64) * INTER + k0 + a_c];
        const float* p0 = &B[(size_t)(k0 + b_r) * HID + n0 + b_c];
        rb0a = *(const float4*)p0; rb0b = *(const float4*)(p0 + 4);
        const float* p1 = &B[(size_t)(k0 + b_r + 16) * HID + n0 + b_c];
        rb1a = *(const float4*)p1; rb1b = *(const float4*)(p1 + 4);
    };
    auto sts = [&](int buf) {
        *(uint4*)&As[buf][a_r * LDA_S + a_c] = ra0;
        *(uint4*)&As[buf][(a_r + 64) * LDA_S + a_c] = ra1;
        *(uint4*)&Bs[buf][b_r * LDB_S + b_c] = f8_to_bf8(rb0a, rb0b);
        *(uint4*)&Bs[buf][(b_r + 16) * LDB_S + b_c] = f8_to_bf8(rb1a, rb1b);
    };

    const int niter = INTER / BK;
    ldg(0); sts(0); __syncthreads();
    for (int it = 0; it < niter; it++) {
        if (it + 1 < niter) ldg((it + 1) * BK);
        mma_tile(As[it & 1], Bs[it & 1], acc, wm, wn);
        if (it + 1 < niter) { sts((it + 1) & 1); __syncthreads(); }
    }

#pragma unroll
    for (int i = 0; i < 2; i++) {
#pragma unroll
        for (int j = 0; j < 4; j++) {
            wmma::store_matrix_sync(&stage_s[warp * 272], acc[i][j], 16, wmma::mem_row_major);
            __syncwarp();
#pragma unroll
            for (int q = 0; q < 8; q++) {
                int el = lane + q * 32;
                int r = el >> 4, c = el & 15;
                int lr = wm * 32 + i * 16 + r;
                if (m0 + lr < cnt) {
                    int tk = stok[lr];
                    atomicAdd(&out[(size_t)tk * HID + n0 + wn * 64 + j * 16 + c],
                              stage_s[warp * 272 + r * 16 + c]);
                }
            }
            __syncwarp();
        }
    }
}

// ---------------------------------------------------------------------------
// Launch
// ---------------------------------------------------------------------------
extern "C" void kernel_launch(void* const* d_in, const int* in_sizes, int n_in,
                              void* d_out, int out_size) {
    const int*   positions = (const int*)  d_in[0];
    const float* hidden    = (const float*)d_in[1];
    const float* Wqkv      = (const float*)d_in[2];
    const float* Wo        = (const float*)d_in[3];
    const float* qnw       = (const float*)d_in[4];
    const float* knw       = (const float*)d_in[5];
    const float* inln      = (const float*)d_in[6];
    const float* postln    = (const float*)d_in[7];
    const float* Wg        = (const float*)d_in[8];
    const float* Wgu       = (const float*)d_in[9];
    const float* Wd        = (const float*)d_in[10];
    float* out = (float*)d_out;

    __nv_bfloat16 *p_hb, *p_attnb, *p_h2b;
    float *p_qkv, *p_h2;
    cudaGetSymbolAddress((void**)&p_hb,    g_hb);
    cudaGetSymbolAddress((void**)&p_qkv,   g_qkv);
    cudaGetSymbolAddress((void**)&p_h2,    g_h2);
    cudaGetSymbolAddress((void**)&p_h2b,   g_h2b);
    cudaGetSymbolAddress((void**)&p_attnb, g_attnb);

    k_rmsnorm<<<T_TOK, 256>>>(hidden, inln, nullptr, p_hb);
    k_gemm_bf16<<<dim3(QKV_N / BN, T_TOK / BM), 256>>>(p_hb, Wqkv, p_qkv, nullptr,
                                                       T_TOK, QKV_N, HID);
    k_qk_prep<<<dim3(NH + 2 * NKV, T_TOK), 32>>>(positions, qnw, knw);
    k_attn_mma<<<dim3(T_TOK / 64, NH), 128>>>();
    k_gemm_bf16<<<dim3(HID / BN, T_TOK / BM), 256>>>(p_attnb, Wo, out, hidden,
                                                     T_TOK, HID, NH * HD);
    k_rmsnorm<<<T_TOK, 256>>>(out, postln, p_h2, p_h2b);
    k_zero<<<1, 64>>>();
    k_route<<<T_TOK, 64>>>(p_h2, Wg);
    k_scan<<<1, 1>>>();
    k_scatter<<<T_TOK, 8>>>();
    k_moe1<<<dim3(1024 / BN, 8, NE), 256>>>(p_h2b, Wgu);
    k_moe_act<<<(NA_PAD * 128) / 256, 256>>>();
    k_moe2<<<dim3(HID / BN, 8, NE), 256>>>(Wd, out);
}